// round 4
// baseline (speedup 1.0000x reference)
#include <cuda_runtime.h>
#include <cuda_bf16.h>
#include <math.h>

#define PER    12
#define NHEAD  12
#define NCOL   76          // floats per pred row = 19 float4 exactly
#define TILE   64          // rows per tile (== TPB)
#define TPB    64

__device__ __forceinline__ unsigned smem_u32(const void* p) {
    return (unsigned)__cvta_generic_to_shared(p);
}
__device__ __forceinline__ void cpa16(unsigned dst, const void* src) {
    asm volatile("cp.async.cg.shared.global [%0], [%1], 16;" :: "r"(dst), "l"(src));
}
__device__ __forceinline__ void cpa4(unsigned dst, const void* src) {
    asm volatile("cp.async.ca.shared.global [%0], [%1], 4;" :: "r"(dst), "l"(src));
}

__shared__ float pred_s[2][TILE * NCOL];   // 2 x 19456 B
__shared__ float roi_s [2][TILE * 7];      // 2 x  1792 B   (total 42496 B)

__device__ __forceinline__ void issue_tile(const float* __restrict__ pred,
                                           const float* __restrict__ roi,
                                           int t, int b, int N, int tid)
{
    const int r0   = t * TILE;
    const int rows = min(TILE, N - r0);
    const char* psrc = (const char*)(pred + (size_t)r0 * NCOL);
    const unsigned sp = smem_u32(&pred_s[b][0]);
    const char* rsrc = (const char*)(roi + (size_t)r0 * 7);
    const unsigned sr = smem_u32(&roi_s[b][0]);

    if (rows == TILE) {
        #pragma unroll
        for (int i = 0; i < 19; i++) {
            int idx = tid + i * TPB;
            cpa16(sp + idx * 16, psrc + idx * 16);
        }
        // roi tile = 64*7 floats = 112 float4, base byte offset t*1792 (16B aligned)
        #pragma unroll
        for (int i = 0; i < 2; i++) {
            int idx = tid + i * TPB;
            if (idx < (TILE * 7) / 4)
                cpa16(sr + idx * 16, rsrc + idx * 16);
        }
    } else {
        const int n4 = rows * 19;          // tail rows are still whole float4s
        for (int i = tid; i < n4; i += TPB)
            cpa16(sp + i * 16, psrc + i * 16);
        for (int i = tid; i < rows * 7; i += TPB)
            cpa4(sr + i * 4, rsrc + i * 4);
    }
}

__global__ __launch_bounds__(TPB)
void rpn_decode_kernel(const float* __restrict__ roi,
                       const float* __restrict__ pred,
                       const float* __restrict__ anchor,
                       float* __restrict__ out,
                       int N, int ntiles)
{
    const int tid    = threadIdx.x;
    const int stride = gridDim.x;
    int t = blockIdx.x;
    if (t >= ntiles) return;

    const float a0 = __ldg(anchor + 0);
    const float a1 = __ldg(anchor + 1);
    const float a2 = __ldg(anchor + 2);

    // prologue: prefetch first tile into buffer 0
    issue_tile(pred, roi, t, 0, N, tid);
    asm volatile("cp.async.commit_group;" ::: "memory");

    int b = 0;
    for (; t < ntiles; t += stride, b ^= 1) {
        const int tn = t + stride;
        const bool has_next = tn < ntiles;
        if (has_next) {
            issue_tile(pred, roi, tn, b ^ 1, N, tid);
            asm volatile("cp.async.commit_group;" ::: "memory");
            asm volatile("cp.async.wait_group 1;" ::: "memory");
        } else {
            asm volatile("cp.async.wait_group 0;" ::: "memory");
        }
        __syncthreads();

        const int row0 = t * TILE;
        const int rows = min(TILE, N - row0);

        // ---- per-row decode; thread tid owns row tid of this tile ----
        if (tid < rows) {
            const float* p = &pred_s[b][tid * NCOL];

            int   xb = 0; float xm = p[0];  float xres = p[24];
            #pragma unroll
            for (int i = 1; i < PER; i++) {
                float v = p[i];
                if (v > xm) { xm = v; xb = i; xres = p[24 + i]; }
            }
            int   zb = 0; float zm = p[12]; float zres = p[36];
            #pragma unroll
            for (int i = 1; i < PER; i++) {
                float v = p[12 + i];
                if (v > zm) { zm = v; zb = i; zres = p[36 + i]; }
            }
            int   rb = 0; float rm = p[49]; float rres = p[61];
            #pragma unroll
            for (int i = 1; i < NHEAD; i++) {
                float v = p[49 + i];
                if (v > rm) { rm = v; rb = i; rres = p[61 + i]; }
            }

            float y_off = p[48];
            float ph = p[73], pw = p[74], pl = p[75];

            float roi_x  = roi_s[b][tid * 7 + 0];
            float roi_y  = roi_s[b][tid * 7 + 1];
            float roi_z  = roi_s[b][tid * 7 + 2];
            float roi_ry = roi_s[b][tid * 7 + 6];

            const float LOC_BIN = 0.5f;
            float pos_x = (float)xb * LOC_BIN + 0.25f - 3.0f + xres * LOC_BIN;
            float pos_z = (float)zb * LOC_BIN + 0.25f - 3.0f + zres * LOC_BIN;
            float pos_y = roi_y + y_off;

            const float TWO_PI = 6.2831853071795864769f;
            const float PI_F   = 3.1415926535897932385f;
            const float APC    = TWO_PI / (float)NHEAD;
            float ry = (float)rb * APC + rres * (APC * 0.5f);
            ry = fmodf(ry, TWO_PI);
            if (ry < 0.0f) ry += TWO_PI;   // jnp floor-mod
            if (ry > PI_F) ry -= TWO_PI;

            float h = fmaf(ph, a0, a0);
            float w = fmaf(pw, a1, a1);
            float l = fmaf(pl, a2, a2);

            float s, c;
            sincosf(roi_ry, &s, &c);       // cos(-x)=c, sin(-x)=-s
            float cn = c, sn = -s;
            float x_rot = pos_x * cn - pos_z * sn;
            float z_rot = pos_x * sn + pos_z * cn;

            // stage results in place (owner thread already consumed this row)
            float* o = &pred_s[b][tid * NCOL];
            o[0] = x_rot + roi_x;
            o[1] = pos_y;
            o[2] = z_rot + roi_z;
            o[3] = h;
            o[4] = w;
            o[5] = l;
            o[6] = ry + roi_ry;
        }
        __syncthreads();

        // ---- coalesced stage-out ----
        float* obase = out + (size_t)row0 * 7;
        const int nout = rows * 7;
        #pragma unroll
        for (int k = 0; k < 7; k++) {
            int j = k * TPB + tid;
            if (j < nout) {
                int r = j / 7;
                int c = j - r * 7;
                obase[j] = pred_s[b][r * NCOL + c];
            }
        }
        __syncthreads();   // buffer b may be refilled next iteration
    }
}

extern "C" void kernel_launch(void* const* d_in, const int* in_sizes, int n_in,
                              void* d_out, int out_size)
{
    const float* roi    = (const float*)d_in[0];   // (N,7)
    const float* pred   = (const float*)d_in[1];   // (N,76)
    const float* anchor = (const float*)d_in[2];   // (3,)
    float* out = (float*)d_out;                    // (N,7)

    int N = in_sizes[0] / 7;
    int ntiles = (N + TILE - 1) / TILE;
    int grid = 152 * 5;                 // persistent: 5 CTAs/SM on 152 SMs
    if (grid > ntiles) grid = ntiles;
    rpn_decode_kernel<<<grid, TPB>>>(roi, pred, anchor, out, N, ntiles);
}

// round 5
// speedup vs baseline: 1.0403x; 1.0403x over previous
#include <cuda_runtime.h>
#include <cuda_bf16.h>
#include <math.h>

#define PER    12
#define NHEAD  12
#define NCOL   76          // floats per pred row = 19 float4 exactly
#define TILE   128         // rows per CTA (4 warps x 32 rows)
#define TPB    128

__device__ __forceinline__ unsigned smem_u32(const void* p) {
    return (unsigned)__cvta_generic_to_shared(p);
}
__device__ __forceinline__ void cpa16(unsigned dst, const void* src) {
    asm volatile("cp.async.cg.shared.global [%0], [%1], 16;" :: "r"(dst), "l"(src));
}
__device__ __forceinline__ void cpa4(unsigned dst, const void* src) {
    asm volatile("cp.async.ca.shared.global [%0], [%1], 4;" :: "r"(dst), "l"(src));
}

__global__ __launch_bounds__(TPB)
void rpn_decode_kernel(const float* __restrict__ roi,
                       const float* __restrict__ pred,
                       const float* __restrict__ anchor,
                       float* __restrict__ out,
                       int N)
{
    __shared__ float pred_s[TILE * NCOL];   // 38912 B
    __shared__ float roi_s [TILE * 7];      //  3584 B  (42496 B total)

    const int tid  = threadIdx.x;
    const int wid  = tid >> 5;
    const int lane = tid & 31;

    // each warp owns 32 consecutive rows; no inter-warp coupling at all
    const int wrow0 = blockIdx.x * TILE + wid * 32;   // global first row of this warp
    if (wrow0 >= N) return;
    const int wrows = min(32, N - wrow0);

    float* wpred = pred_s + wid * 32 * NCOL;          // this warp's smem slice
    float* wroi  = roi_s  + wid * 32 * 7;

    // ---- warp-local stage-in via cp.async (own group, own wait) ----
    const char* psrc = (const char*)(pred + (size_t)wrow0 * NCOL);  // 16B aligned
    const unsigned sp = smem_u32(wpred);
    const char* rsrc = (const char*)(roi + (size_t)wrow0 * 7);      // 16B aligned
    const unsigned sr = smem_u32(wroi);

    if (wrows == 32) {
        #pragma unroll
        for (int k = 0; k < 19; k++) {                // 608 float4s / warp
            int idx = lane + 32 * k;
            cpa16(sp + idx * 16, psrc + idx * 16);
        }
        #pragma unroll
        for (int k = 0; k < 2; k++) {                 // 56 float4s / warp
            int idx = lane + 32 * k;
            if (idx < 56)
                cpa16(sr + idx * 16, rsrc + idx * 16);
        }
    } else {
        for (int i = lane; i < wrows * 19; i += 32)   // tail rows: whole float4s
            cpa16(sp + i * 16, psrc + i * 16);
        for (int i = lane; i < wrows * 7; i += 32)
            cpa4(sr + i * 4, rsrc + i * 4);
    }
    asm volatile("cp.async.commit_group;" ::: "memory");

    const float a0 = __ldg(anchor + 0);
    const float a1 = __ldg(anchor + 1);
    const float a2 = __ldg(anchor + 2);

    asm volatile("cp.async.wait_group 0;" ::: "memory");
    __syncwarp();

    // ---- per-row decode: lane owns row wrow0+lane ----
    if (lane < wrows) {
        const float* p = wpred + lane * NCOL;

        int   xb = 0; float xm = p[0];  float xres = p[24];
        #pragma unroll
        for (int i = 1; i < PER; i++) {
            float v = p[i];
            if (v > xm) { xm = v; xb = i; xres = p[24 + i]; }
        }
        int   zb = 0; float zm = p[12]; float zres = p[36];
        #pragma unroll
        for (int i = 1; i < PER; i++) {
            float v = p[12 + i];
            if (v > zm) { zm = v; zb = i; zres = p[36 + i]; }
        }
        int   rb = 0; float rm = p[49]; float rres = p[61];
        #pragma unroll
        for (int i = 1; i < NHEAD; i++) {
            float v = p[49 + i];
            if (v > rm) { rm = v; rb = i; rres = p[61 + i]; }
        }

        float y_off = p[48];
        float ph = p[73], pw = p[74], pl = p[75];

        float roi_x  = wroi[lane * 7 + 0];
        float roi_y  = wroi[lane * 7 + 1];
        float roi_z  = wroi[lane * 7 + 2];
        float roi_ry = wroi[lane * 7 + 6];

        const float LOC_BIN = 0.5f;
        float pos_x = (float)xb * LOC_BIN + 0.25f - 3.0f + xres * LOC_BIN;
        float pos_z = (float)zb * LOC_BIN + 0.25f - 3.0f + zres * LOC_BIN;
        float pos_y = roi_y + y_off;

        const float TWO_PI = 6.2831853071795864769f;
        const float PI_F   = 3.1415926535897932385f;
        const float APC    = TWO_PI / (float)NHEAD;
        float ry = (float)rb * APC + rres * (APC * 0.5f);
        ry = fmodf(ry, TWO_PI);
        if (ry < 0.0f) ry += TWO_PI;   // jnp floor-mod
        if (ry > PI_F) ry -= TWO_PI;

        float h = fmaf(ph, a0, a0);
        float w = fmaf(pw, a1, a1);
        float l = fmaf(pl, a2, a2);

        float s, c;
        sincosf(roi_ry, &s, &c);       // cos(-x)=c, sin(-x)=-s
        float cn = c, sn = -s;
        float x_rot = pos_x * cn - pos_z * sn;
        float z_rot = pos_x * sn + pos_z * cn;

        // stage results into own row slot (owner already consumed the row)
        float* o = wpred + lane * NCOL;
        o[0] = x_rot + roi_x;
        o[1] = pos_y;
        o[2] = z_rot + roi_z;
        o[3] = h;
        o[4] = w;
        o[5] = l;
        o[6] = ry + roi_ry;
    }
    __syncwarp();

    // ---- warp-local vectorized stage-out: 32 rows x 7 = 56 float4 ----
    if (wrows == 32) {
        float4* obase4 = reinterpret_cast<float4*>(out + (size_t)wrow0 * 7); // 16B aligned
        #pragma unroll
        for (int k = 0; k < 2; k++) {
            int j = lane + 32 * k;          // float4 index, 56 total
            if (j < 56) {
                int e = j * 4;
                float4 v;
                int r0 = e / 7,       c0 = e - r0 * 7;
                int r1 = (e+1) / 7,   c1 = (e+1) - r1 * 7;
                int r2 = (e+2) / 7,   c2 = (e+2) - r2 * 7;
                int r3 = (e+3) / 7,   c3 = (e+3) - r3 * 7;
                v.x = wpred[r0 * NCOL + c0];
                v.y = wpred[r1 * NCOL + c1];
                v.z = wpred[r2 * NCOL + c2];
                v.w = wpred[r3 * NCOL + c3];
                obase4[j] = v;
            }
        }
    } else {
        float* obase = out + (size_t)wrow0 * 7;
        for (int i = lane; i < wrows * 7; i += 32) {
            int r = i / 7, c = i - r * 7;
            obase[i] = wpred[r * NCOL + c];
        }
    }
}

extern "C" void kernel_launch(void* const* d_in, const int* in_sizes, int n_in,
                              void* d_out, int out_size)
{
    const float* roi    = (const float*)d_in[0];   // (N,7)
    const float* pred   = (const float*)d_in[1];   // (N,76)
    const float* anchor = (const float*)d_in[2];   // (3,)
    float* out = (float*)d_out;                    // (N,7)

    int N = in_sizes[0] / 7;
    int blocks = (N + TILE - 1) / TILE;
    rpn_decode_kernel<<<blocks, TPB>>>(roi, pred, anchor, out, N);
}